// round 15
// baseline (speedup 1.0000x reference)
#include <cuda_runtime.h>

// Problem constants
#define T_STEPS 500
#define BATCH   1024
#define NDIM    256
#define ALPHA_F 0.995f   // 1 - 0.05/10
#define VTH_F   1.0f

#define TPB        256
#define C_BLOCKS   4                           // consumer blocks (first in grid)
#define ROWS_PB    40                          // 5 rows/warp x 8 warps (R7 shape)
#define ROWS_PW    5
#define N_ROWS     (T_STEPS * BATCH)           // 512000
#define P_BLOCKS   (N_ROWS / ROWS_PB)          // 12800 one-shot producer blocks

#define GROUP      4                           // consumer double-buffer depth

// Readiness protocol (no init kernel needed):
//   g_s word == 0x00000000  -> not ready (zero-init on load; re-poisoned by
//                              the consumer after each read for graph replays)
//   otherwise               -> word = ~bits(s). 0 is unreachable: it would
//                              require s = NaN, impossible from finite dot.
__device__ unsigned g_s[T_STEPS * BATCH];      // 2 MB, L2-resident

__device__ __forceinline__ unsigned ld_relaxed_gpu_u32(const unsigned* p) {
    unsigned v;
    asm volatile("ld.relaxed.gpu.global.u32 %0, [%1];" : "=r"(v) : "l"(p) : "memory");
    return v;
}

// ---------------------------------------------------------------------------
// Single fused kernel. Producers: one-shot, 40 rows, ZERO sync instructions.
// ---------------------------------------------------------------------------
__global__ void __launch_bounds__(TPB) lif_fused_kernel(
    const float* __restrict__ x,      // [T, B, N]
    const float* __restrict__ w,      // [N]
    float* __restrict__ out)          // [2, T, B]  (v then z)
{
    const int tid = threadIdx.x;

    if (blockIdx.x >= C_BLOCKS) {
        // ===== PRODUCER: R7 warp body (5 rows/warp, 10 float4 in flight) =====
        const int warp = tid >> 5;
        const int lane = tid & 31;
        const long long rbase =
            (long long)(blockIdx.x - C_BLOCKS) * ROWS_PB + warp * ROWS_PW;

        const float4* wv = reinterpret_cast<const float4*>(w);
        const float4 w0 = wv[lane];
        const float4 w1 = wv[lane + 32];

        float4 a[2 * ROWS_PW];
        #pragma unroll
        for (int i = 0; i < ROWS_PW; ++i) {
            const float4* xr =
                reinterpret_cast<const float4*>(x + (rbase + i) * NDIM);
            a[2 * i]     = xr[lane];
            a[2 * i + 1] = xr[lane + 32];
        }

        float acc[ROWS_PW];
        #pragma unroll
        for (int i = 0; i < ROWS_PW; ++i) {
            const float4 p0 = a[2 * i], p1 = a[2 * i + 1];
            acc[i] = p0.x * w0.x + p0.y * w0.y + p0.z * w0.z + p0.w * w0.w
                   + p1.x * w1.x + p1.y * w1.y + p1.z * w1.z + p1.w * w1.w;
        }
        #pragma unroll
        for (int off = 16; off > 0; off >>= 1) {
            #pragma unroll
            for (int i = 0; i < ROWS_PW; ++i)
                acc[i] += __shfl_xor_sync(0xffffffffu, acc[i], off);
        }
        if (lane == 0) {
            #pragma unroll
            for (int i = 0; i < ROWS_PW; ++i)
                g_s[rbase + i] = ~__float_as_uint(acc[i]);   // != 0 always
        }
        // exit — no sync of any kind
    } else {
        // ===== CONSUMER: persistent, 4-deep double buffer, re-poisons =====
        const int b = blockIdx.x * TPB + tid;   // 0..1023
        float* __restrict__ vout = out;                               // [T, B]
        float* __restrict__ zout = out + (long long)T_STEPS * BATCH;  // [T, B]

        float v = 0.0f, z = 0.0f;
        unsigned cur[GROUP], nxt[GROUP];

        #pragma unroll
        for (int i = 0; i < GROUP; ++i)
            cur[i] = ld_relaxed_gpu_u32(&g_s[i * BATCH + b]);

        #pragma unroll 1
        for (int t = 0; t < T_STEPS; t += GROUP) {
            const int tn = t + GROUP;
            if (tn < T_STEPS) {
                #pragma unroll
                for (int i = 0; i < GROUP; ++i)
                    nxt[i] = ld_relaxed_gpu_u32(&g_s[(tn + i) * BATCH + b]);
            }

            #pragma unroll
            for (int i = 0; i < GROUP; ++i) {
                const long long idx = (long long)(t + i) * BATCH + b;
                while (cur[i] == 0u)                 // not ready yet
                    cur[i] = ld_relaxed_gpu_u32(&g_s[idx]);
                g_s[idx] = 0u;                       // re-poison for next replay

                const float s = __uint_as_float(~cur[i]);
                v = ALPHA_F * v + s - z;
                z = (v > VTH_F) ? 1.0f : 0.0f;
                vout[idx] = v;                       // same [T,B] layout as g_s
                zout[idx] = z;
            }

            #pragma unroll
            for (int i = 0; i < GROUP; ++i)
                cur[i] = nxt[i];
        }
    }
}

// ---------------------------------------------------------------------------
extern "C" void kernel_launch(void* const* d_in, const int* in_sizes, int n_in,
                              void* d_out, int out_size)
{
    const float* x = (const float*)d_in[0];   // [T, B, N] fp32
    const float* w = (const float*)d_in[1];   // [N] fp32
    float* out = (float*)d_out;               // [2, T, B] fp32

    lif_fused_kernel<<<C_BLOCKS + P_BLOCKS, TPB>>>(x, w, out);
}